// round 4
// baseline (speedup 1.0000x reference)
#include <cuda_runtime.h>
#include <cuda_bf16.h>
#include <cstdint>

#define NN 100000
#define NE 1600000
#define DDIM 128
#define BN_EPS 1e-5f
#define PA 136                         // bf16 SMEM row pitch for A planes
#define SMEM_A_BYTES (2 * 128 * PA * 2)      // 69632
#define SMEM_BYTES (SMEM_A_BYTES + 65536)    // + W fragment blob = 135168
#define SCAN_NB ((NN + 1023) / 1024)   // 98

// ---------------- device scratch (static globals: allowed) ----------------
__device__ float g_z[(size_t)NN * DDIM];
__device__ __nv_bfloat16 g_Ahi[(size_t)NN * DDIM];
__device__ __nv_bfloat16 g_Alo[(size_t)NN * DDIM];
__device__ int g_deg[NN];
__device__ int g_off[NN + 1];
__device__ int g_cur[NN];
__device__ int2 g_se[NE];
__device__ int g_btot[SCAN_NB];
__device__ uint32_t g_Wfrag[6 * 16384];   // 6 matrices, fragment-major
__device__ float g_bsum[3][DDIM];
__device__ float g_bsq[3][DDIM];

// ---------------- helpers ----------------
__device__ __forceinline__ void split2(float a, float b, uint32_t& hi, uint32_t& lo) {
    __nv_bfloat16 ah = __float2bfloat16(a), bh = __float2bfloat16(b);
    __nv_bfloat16 al = __float2bfloat16(a - __bfloat162float(ah));
    __nv_bfloat16 bl = __float2bfloat16(b - __bfloat162float(bh));
    __nv_bfloat162 H; H.x = ah; H.y = bh;
    __nv_bfloat162 L; L.x = al; L.y = bl;
    hi = *reinterpret_cast<uint32_t*>(&H);
    lo = *reinterpret_cast<uint32_t*>(&L);
}

__device__ __forceinline__ uint32_t lds_u32(const __nv_bfloat16* p) {
    return *reinterpret_cast<const uint32_t*>(p);
}

__device__ __forceinline__ int Foff(int i) {
    return (i == 0) ? 0 : (g_off[i] + g_btot[(i - 1) >> 10]);
}

#define MMA16816(d0,d1,d2,d3,a0,a1,a2,a3,b0,b1)                               \
    asm volatile("mma.sync.aligned.m16n8k16.row.col.f32.bf16.bf16.f32 "       \
                 "{%0,%1,%2,%3},{%4,%5,%6,%7},{%8,%9},{%0,%1,%2,%3};"         \
                 : "+f"(d0), "+f"(d1), "+f"(d2), "+f"(d3)                     \
                 : "r"(a0), "r"(a1), "r"(a2), "r"(a3), "r"(b0), "r"(b1))

// ---------------- setup: W fragment-major split + zero deg/cur/BN ----------
__global__ void k_setup(const float* __restrict__ W1, const float* __restrict__ W2) {
    int i = blockIdx.x * blockDim.x + threadIdx.x;
    if (i < 6 * 16384) {
        int part = i & 3;              // 0=b0h 1=b1h 2=b0l 3=b1l
        int lane = (i >> 2) & 31;
        int fragid = (i >> 7) & 127;   // nt*8 + kk
        int mat = i >> 14;             // l*2 + j
        int l = mat >> 1, j = mat & 1;
        int nt = fragid >> 3, kk = fragid & 7;
        int bn = nt * 8 + (lane >> 2);
        int bk = kk * 16 + (lane & 3) * 2 + (part & 1) * 8;
        const float* Wsrc = (j ? W2 : W1) + (size_t)l * 16384;
        float w0 = Wsrc[bk * 128 + bn];
        float w1 = Wsrc[(bk + 1) * 128 + bn];
        uint32_t hi, lo;
        split2(w0, w1, hi, lo);
        g_Wfrag[i] = (part >= 2) ? lo : hi;
    }
    if (i < NN) { g_deg[i] = 0; g_cur[i] = 0; }
    if (i < 3 * DDIM) {
        ((float*)g_bsum)[i] = 0.f;
        ((float*)g_bsq)[i] = 0.f;
    }
}

__global__ void k_hist(const int* __restrict__ dst) {
    int e = blockIdx.x * blockDim.x + threadIdx.x;
    if (e < NE) atomicAdd(&g_deg[__ldg(dst + e)], 1);
}

// ---------------- two-level scan (final offsets materialized lazily) -------
__global__ void k_scan1() {
    __shared__ int wsum[32];
    int tid = threadIdx.x, lane = tid & 31, wid = tid >> 5;
    int i = blockIdx.x * 1024 + tid;
    int v = (i < NN) ? g_deg[i] : 0;
    int x = v;
#pragma unroll
    for (int d = 1; d < 32; d <<= 1) {
        int t = __shfl_up_sync(0xffffffff, x, d);
        if (lane >= d) x += t;
    }
    if (lane == 31) wsum[wid] = x;
    __syncthreads();
    if (wid == 0) {
        int y = wsum[lane];
#pragma unroll
        for (int d = 1; d < 32; d <<= 1) {
            int t = __shfl_up_sync(0xffffffff, y, d);
            if (lane >= d) y += t;
        }
        wsum[lane] = y;
    }
    __syncthreads();
    int incl = x + (wid ? wsum[wid - 1] : 0);
    if (i < NN) g_off[i + 1] = incl;
    if (tid == 1023) g_btot[blockIdx.x] = incl;
}

__global__ void k_scan2() {   // 1 block, scans SCAN_NB block totals -> exclusive
    __shared__ int ws[4];
    int tid = threadIdx.x, lane = tid & 31, wid = tid >> 5;
    int v = (tid < SCAN_NB) ? g_btot[tid] : 0;
    int x = v;
#pragma unroll
    for (int d = 1; d < 32; d <<= 1) {
        int t = __shfl_up_sync(0xffffffff, x, d);
        if (lane >= d) x += t;
    }
    if (lane == 31) ws[wid] = x;
    __syncthreads();
    if (tid == 0) {
        int r = 0;
#pragma unroll
        for (int j = 0; j < 4; j++) { int t = ws[j]; ws[j] = r; r += t; }
    }
    __syncthreads();
    int incl = x + ws[wid];
    if (tid < SCAN_NB) g_btot[tid] = incl - v;   // exclusive block base
}

__global__ void k_scatter(const int* __restrict__ src, const int* __restrict__ dst) {
    int e = blockIdx.x * blockDim.x + threadIdx.x;
    if (e >= NE) return;
    int d = __ldg(dst + e);
    int pos = Foff(d) + atomicAdd(&g_cur[d], 1);
    g_se[pos] = make_int2(__ldg(src + e), e);
}

// ---------------- aggregation: warp per node, fused BN on gather ----------
__global__ void k_agg(const float* __restrict__ x, const float* __restrict__ ea,
                      const float* __restrict__ eps,
                      const float* __restrict__ gamma, const float* __restrict__ beta,
                      int l, int first) {
    int node = (blockIdx.x * blockDim.x + threadIdx.x) >> 5;
    if (node >= NN) return;
    int lane = threadIdx.x & 31;
    int beg = Foff(node);
    int end = g_off[node + 1] + g_btot[node >> 10];
    float4 acc = make_float4(0.f, 0.f, 0.f, 0.f);
    float4 hn;

    if (first) {
        const float4* hin = (const float4*)x;
        int i = beg;
        for (; i + 2 <= end; i += 2) {
            int2 a = g_se[i];
            int2 b = g_se[i + 1];
            float4 h0 = hin[(size_t)a.x * 32 + lane];
            float4 e0 = __ldcs(((const float4*)ea) + (size_t)a.y * 32 + lane);
            float4 h1 = hin[(size_t)b.x * 32 + lane];
            float4 e1 = __ldcs(((const float4*)ea) + (size_t)b.y * 32 + lane);
            acc.x += fmaxf(h0.x + e0.x, 0.f) + fmaxf(h1.x + e1.x, 0.f);
            acc.y += fmaxf(h0.y + e0.y, 0.f) + fmaxf(h1.y + e1.y, 0.f);
            acc.z += fmaxf(h0.z + e0.z, 0.f) + fmaxf(h1.z + e1.z, 0.f);
            acc.w += fmaxf(h0.w + e0.w, 0.f) + fmaxf(h1.w + e1.w, 0.f);
        }
        if (i < end) {
            int2 a = g_se[i];
            float4 h0 = hin[(size_t)a.x * 32 + lane];
            float4 e0 = __ldcs(((const float4*)ea) + (size_t)a.y * 32 + lane);
            acc.x += fmaxf(h0.x + e0.x, 0.f);
            acc.y += fmaxf(h0.y + e0.y, 0.f);
            acc.z += fmaxf(h0.z + e0.z, 0.f);
            acc.w += fmaxf(h0.w + e0.w, 0.f);
        }
        hn = hin[(size_t)node * 32 + lane];
    } else {
        // BN scale/shift for previous layer, this lane's 4 columns
        int lm = l - 1;
        float4 bs, bt;
        {
            float invN = 1.f / (float)NN;
            int c = lane * 4;
            float mu, var, s;
            mu = g_bsum[lm][c + 0] * invN; var = g_bsq[lm][c + 0] * invN - mu * mu;
            s = __ldg(gamma + lm * 128 + c + 0) * rsqrtf(var + BN_EPS);
            bs.x = s; bt.x = __ldg(beta + lm * 128 + c + 0) - mu * s;
            mu = g_bsum[lm][c + 1] * invN; var = g_bsq[lm][c + 1] * invN - mu * mu;
            s = __ldg(gamma + lm * 128 + c + 1) * rsqrtf(var + BN_EPS);
            bs.y = s; bt.y = __ldg(beta + lm * 128 + c + 1) - mu * s;
            mu = g_bsum[lm][c + 2] * invN; var = g_bsq[lm][c + 2] * invN - mu * mu;
            s = __ldg(gamma + lm * 128 + c + 2) * rsqrtf(var + BN_EPS);
            bs.z = s; bt.z = __ldg(beta + lm * 128 + c + 2) - mu * s;
            mu = g_bsum[lm][c + 3] * invN; var = g_bsq[lm][c + 3] * invN - mu * mu;
            s = __ldg(gamma + lm * 128 + c + 3) * rsqrtf(var + BN_EPS);
            bs.w = s; bt.w = __ldg(beta + lm * 128 + c + 3) - mu * s;
        }
        const float4* zin = (const float4*)g_z;
        int i = beg;
        for (; i + 2 <= end; i += 2) {
            int2 a = g_se[i];
            int2 b = g_se[i + 1];
            float4 g0 = zin[(size_t)a.x * 32 + lane];
            float4 e0 = __ldcs(((const float4*)ea) + (size_t)a.y * 32 + lane);
            float4 g1 = zin[(size_t)b.x * 32 + lane];
            float4 e1 = __ldcs(((const float4*)ea) + (size_t)b.y * 32 + lane);
            float4 h0, h1;
            h0.x = fmaxf(bs.x * g0.x + bt.x, 0.f); h1.x = fmaxf(bs.x * g1.x + bt.x, 0.f);
            h0.y = fmaxf(bs.y * g0.y + bt.y, 0.f); h1.y = fmaxf(bs.y * g1.y + bt.y, 0.f);
            h0.z = fmaxf(bs.z * g0.z + bt.z, 0.f); h1.z = fmaxf(bs.z * g1.z + bt.z, 0.f);
            h0.w = fmaxf(bs.w * g0.w + bt.w, 0.f); h1.w = fmaxf(bs.w * g1.w + bt.w, 0.f);
            acc.x += fmaxf(h0.x + e0.x, 0.f) + fmaxf(h1.x + e1.x, 0.f);
            acc.y += fmaxf(h0.y + e0.y, 0.f) + fmaxf(h1.y + e1.y, 0.f);
            acc.z += fmaxf(h0.z + e0.z, 0.f) + fmaxf(h1.z + e1.z, 0.f);
            acc.w += fmaxf(h0.w + e0.w, 0.f) + fmaxf(h1.w + e1.w, 0.f);
        }
        if (i < end) {
            int2 a = g_se[i];
            float4 g0 = zin[(size_t)a.x * 32 + lane];
            float4 e0 = __ldcs(((const float4*)ea) + (size_t)a.y * 32 + lane);
            float4 h0;
            h0.x = fmaxf(bs.x * g0.x + bt.x, 0.f);
            h0.y = fmaxf(bs.y * g0.y + bt.y, 0.f);
            h0.z = fmaxf(bs.z * g0.z + bt.z, 0.f);
            h0.w = fmaxf(bs.w * g0.w + bt.w, 0.f);
            acc.x += fmaxf(h0.x + e0.x, 0.f);
            acc.y += fmaxf(h0.y + e0.y, 0.f);
            acc.z += fmaxf(h0.z + e0.z, 0.f);
            acc.w += fmaxf(h0.w + e0.w, 0.f);
        }
        float4 gn = zin[(size_t)node * 32 + lane];
        hn.x = fmaxf(bs.x * gn.x + bt.x, 0.f);
        hn.y = fmaxf(bs.y * gn.y + bt.y, 0.f);
        hn.z = fmaxf(bs.z * gn.z + bt.z, 0.f);
        hn.w = fmaxf(bs.w * gn.w + bt.w, 0.f);
    }

    float el = 1.f + __ldg(eps + l);
    float zx = el * hn.x + acc.x;
    float zy = el * hn.y + acc.y;
    float zz = el * hn.z + acc.z;
    float zw = el * hn.w + acc.w;
    size_t o = (size_t)node * DDIM + lane * 4;
    uint32_t h01, l01, h23, l23;
    split2(zx, zy, h01, l01);
    split2(zz, zw, h23, l23);
    *(uint32_t*)(g_Ahi + o)     = h01;
    *(uint32_t*)(g_Ahi + o + 2) = h23;
    *(uint32_t*)(g_Alo + o)     = l01;
    *(uint32_t*)(g_Alo + o + 2) = l23;
}

// ---------------- fused MLP (2 GEMMs) + BN'd residual + BN partials --------
__device__ __forceinline__ void gemm_tile(const __nv_bfloat16* __restrict__ sA_hi,
                                          const __nv_bfloat16* __restrict__ sA_lo,
                                          const uint4* __restrict__ sWf,
                                          float* acc, int lane, int mrow) {
    uint32_t ah[8][4], al[8][4];
    int r0 = mrow + (lane >> 2);
    int cb = (lane & 3) * 2;
#pragma unroll
    for (int kk = 0; kk < 8; kk++) {
        int c = kk * 16 + cb;
        ah[kk][0] = lds_u32(&sA_hi[r0 * PA + c]);
        ah[kk][1] = lds_u32(&sA_hi[(r0 + 8) * PA + c]);
        ah[kk][2] = lds_u32(&sA_hi[r0 * PA + c + 8]);
        ah[kk][3] = lds_u32(&sA_hi[(r0 + 8) * PA + c + 8]);
        al[kk][0] = lds_u32(&sA_lo[r0 * PA + c]);
        al[kk][1] = lds_u32(&sA_lo[(r0 + 8) * PA + c]);
        al[kk][2] = lds_u32(&sA_lo[r0 * PA + c + 8]);
        al[kk][3] = lds_u32(&sA_lo[(r0 + 8) * PA + c + 8]);
    }
#pragma unroll
    for (int nt = 0; nt < 16; nt++) {
        float* d = acc + nt * 4;
#pragma unroll
        for (int kk = 0; kk < 8; kk++) {
            uint4 w = sWf[(nt * 8 + kk) * 32 + lane];
            MMA16816(d[0], d[1], d[2], d[3],
                     ah[kk][0], ah[kk][1], ah[kk][2], ah[kk][3], w.x, w.y);
            MMA16816(d[0], d[1], d[2], d[3],
                     al[kk][0], al[kk][1], al[kk][2], al[kk][3], w.x, w.y);
            MMA16816(d[0], d[1], d[2], d[3],
                     ah[kk][0], ah[kk][1], ah[kk][2], ah[kk][3], w.z, w.w);
        }
    }
}

__global__ void __launch_bounds__(256, 1)
k_mlp(int l, const float* __restrict__ x, const float* __restrict__ masks,
      const float* __restrict__ b1g, const float* __restrict__ b2g,
      const float* __restrict__ gamma, const float* __restrict__ beta, int first) {
    extern __shared__ char smem[];
    __nv_bfloat16* sAhi = (__nv_bfloat16*)smem;
    __nv_bfloat16* sAlo = sAhi + 128 * PA;
    uint4* sWf = (uint4*)(smem + SMEM_A_BYTES);
    float* sZ = (float*)smem;   // reused after GEMM2 (64KB <= SMEM_A_BYTES)
    __shared__ float sBNs[128], sBNt[128];

    int tid = threadIdx.x, lane = tid & 31, warp = tid >> 5;
    int base = blockIdx.x * 128;
    int rows = min(128, NN - base);

    // BN table for residual input transform (layer l-1)
    if (!first && tid < 128) {
        int lm = l - 1;
        float invN = 1.f / (float)NN;
        float mu = g_bsum[lm][tid] * invN;
        float var = g_bsq[lm][tid] * invN - mu * mu;
        float s = __ldg(gamma + lm * 128 + tid) * rsqrtf(var + BN_EPS);
        sBNs[tid] = s;
        sBNt[tid] = __ldg(beta + lm * 128 + tid) - mu * s;
    }

    // load A (z hi/lo planes), zero-fill OOB rows
    for (int i = tid; i < 128 * 64; i += 256) {
        int r = i >> 6, c2 = i & 63;
        uint32_t vh = 0, vl = 0;
        if (r < rows) {
            size_t gi = (size_t)(base + r) * 64 + c2;
            vh = ((const uint32_t*)g_Ahi)[gi];
            vl = ((const uint32_t*)g_Alo)[gi];
        }
        *(uint32_t*)(sAhi + r * PA + c2 * 2) = vh;
        *(uint32_t*)(sAlo + r * PA + c2 * 2) = vl;
    }
    // load W1 fragment blob (coalesced 64KB copy)
    {
        const uint4* wsrc = (const uint4*)(g_Wfrag + (size_t)(l * 2) * 16384);
        for (int i = tid; i < 4096; i += 256) sWf[i] = wsrc[i];
    }
    __syncthreads();

    float acc[64];
#pragma unroll
    for (int i = 0; i < 64; i++) acc[i] = 0.f;
    int mrow = warp * 16;
    gemm_tile(sAhi, sAlo, sWf, acc, lane, mrow);

    // epilogue 1: relu(acc + b1) -> hi/lo back into sA (own rows only)
    int r0 = mrow + (lane >> 2);
    int cb = (lane & 3) * 2;
#pragma unroll
    for (int nt = 0; nt < 16; nt++) {
        int c = nt * 8 + cb;
        float bb0 = __ldg(b1g + l * 128 + c);
        float bb1 = __ldg(b1g + l * 128 + c + 1);
        float v00 = fmaxf(acc[nt * 4 + 0] + bb0, 0.f);
        float v01 = fmaxf(acc[nt * 4 + 1] + bb1, 0.f);
        float v10 = fmaxf(acc[nt * 4 + 2] + bb0, 0.f);
        float v11 = fmaxf(acc[nt * 4 + 3] + bb1, 0.f);
        uint32_t h0, l0, h1, l1;
        split2(v00, v01, h0, l0);
        split2(v10, v11, h1, l1);
        *(uint32_t*)&sAhi[r0 * PA + c] = h0;
        *(uint32_t*)&sAlo[r0 * PA + c] = l0;
        *(uint32_t*)&sAhi[(r0 + 8) * PA + c] = h1;
        *(uint32_t*)&sAlo[(r0 + 8) * PA + c] = l1;
        acc[nt * 4 + 0] = 0.f; acc[nt * 4 + 1] = 0.f;
        acc[nt * 4 + 2] = 0.f; acc[nt * 4 + 3] = 0.f;
    }
    __syncthreads();
    // load W2 fragment blob
    {
        const uint4* wsrc = (const uint4*)(g_Wfrag + (size_t)(l * 2 + 1) * 16384);
        for (int i = tid; i < 4096; i += 256) sWf[i] = wsrc[i];
    }
    __syncthreads();

    gemm_tile(sAhi, sAlo, sWf, acc, lane, mrow);
    __syncthreads();   // everyone done reading sA before sZ overwrite

    // epilogue 2: z = mask * (acc + b2) + x_in,  x_in = relu(bn(z_prev)) or x
    bool ok0 = (base + r0) < NN;
    bool ok1 = (base + r0 + 8) < NN;
    float m0 = ok0 ? __ldg(masks + (size_t)l * NN + base + r0) : 0.f;
    float m1 = ok1 ? __ldg(masks + (size_t)l * NN + base + r0 + 8) : 0.f;
#pragma unroll
    for (int nt = 0; nt < 16; nt++) {
        int c = nt * 8 + cb;
        float bb0 = __ldg(b2g + l * 128 + c);
        float bb1 = __ldg(b2g + l * 128 + c + 1);
        float2 x0 = make_float2(0.f, 0.f), x1 = make_float2(0.f, 0.f);
        if (first) {
            if (ok0) x0 = *(const float2*)(x + (size_t)(base + r0) * 128 + c);
            if (ok1) x1 = *(const float2*)(x + (size_t)(base + r0 + 8) * 128 + c);
        } else {
            if (ok0) {
                float2 g = *(const float2*)(g_z + (size_t)(base + r0) * 128 + c);
                x0.x = fmaxf(sBNs[c] * g.x + sBNt[c], 0.f);
                x0.y = fmaxf(sBNs[c + 1] * g.y + sBNt[c + 1], 0.f);
            }
            if (ok1) {
                float2 g = *(const float2*)(g_z + (size_t)(base + r0 + 8) * 128 + c);
                x1.x = fmaxf(sBNs[c] * g.x + sBNt[c], 0.f);
                x1.y = fmaxf(sBNs[c + 1] * g.y + sBNt[c + 1], 0.f);
            }
        }
        float z00 = m0 * (acc[nt * 4 + 0] + bb0) + x0.x;
        float z01 = m0 * (acc[nt * 4 + 1] + bb1) + x0.y;
        float z10 = m1 * (acc[nt * 4 + 2] + bb0) + x1.x;
        float z11 = m1 * (acc[nt * 4 + 3] + bb1) + x1.y;
        *(float2*)&sZ[r0 * 128 + c] = make_float2(z00, z01);
        *(float2*)&sZ[(r0 + 8) * 128 + c] = make_float2(z10, z11);
    }
    __syncthreads();

    // BN column partials over valid rows
    {
        int c = tid & 127, half = tid >> 7;
        int rbeg = half * 64;
        int rend = min(rbeg + 64, rows);
        float s = 0.f, q = 0.f;
        for (int r = rbeg; r < rend; ++r) {
            float v = sZ[r * 128 + c];
            s += v; q += v * v;
        }
        atomicAdd(&g_bsum[l][c], s);
        atomicAdd(&g_bsq[l][c], q);
    }
    // write z tile
    for (int i = tid; i < rows * 32; i += 256) {
        int r = i >> 5, c4 = i & 31;
        ((float4*)(g_z + (size_t)(base + r) * 128))[c4] = ((const float4*)(sZ + r * 128))[c4];
    }
}

// ---------------- final BN apply + relu (layer 2 only, writes out) ---------
__global__ void k_bn_apply(int l, float* __restrict__ outp,
                           const float* __restrict__ gamma,
                           const float* __restrict__ beta) {
    int idx = blockIdx.x * blockDim.x + threadIdx.x;
    if (idx >= NN * 32) return;
    int c4 = idx & 31;
    int c = c4 * 4;
    float4 z = ((const float4*)g_z)[idx];
    float invN = 1.f / (float)NN;
    float4 r;
    {
        float mu = g_bsum[l][c + 0] * invN;
        float var = g_bsq[l][c + 0] * invN - mu * mu;
        r.x = fmaxf(__ldg(gamma + l * 128 + c + 0) * (z.x - mu) * rsqrtf(var + BN_EPS) + __ldg(beta + l * 128 + c + 0), 0.f);
    }
    {
        float mu = g_bsum[l][c + 1] * invN;
        float var = g_bsq[l][c + 1] * invN - mu * mu;
        r.y = fmaxf(__ldg(gamma + l * 128 + c + 1) * (z.y - mu) * rsqrtf(var + BN_EPS) + __ldg(beta + l * 128 + c + 1), 0.f);
    }
    {
        float mu = g_bsum[l][c + 2] * invN;
        float var = g_bsq[l][c + 2] * invN - mu * mu;
        r.z = fmaxf(__ldg(gamma + l * 128 + c + 2) * (z.z - mu) * rsqrtf(var + BN_EPS) + __ldg(beta + l * 128 + c + 2), 0.f);
    }
    {
        float mu = g_bsum[l][c + 3] * invN;
        float var = g_bsq[l][c + 3] * invN - mu * mu;
        r.w = fmaxf(__ldg(gamma + l * 128 + c + 3) * (z.w - mu) * rsqrtf(var + BN_EPS) + __ldg(beta + l * 128 + c + 3), 0.f);
    }
    ((float4*)outp)[idx] = r;
}

// ---------------- launch ----------------
extern "C" void kernel_launch(void* const* d_in, const int* in_sizes, int n_in,
                              void* d_out, int out_size) {
    const float* x     = (const float*)d_in[0];
    const float* ea    = (const float*)d_in[1];
    const float* masks = (const float*)d_in[2];
    const int*   ei    = (const int*)d_in[3];
    const float* eps   = (const float*)d_in[4];
    const float* W1    = (const float*)d_in[5];
    const float* b1    = (const float*)d_in[6];
    const float* W2    = (const float*)d_in[7];
    const float* b2    = (const float*)d_in[8];
    const float* gamma = (const float*)d_in[9];
    const float* beta  = (const float*)d_in[10];
    float* out = (float*)d_out;

    cudaFuncSetAttribute(k_mlp, cudaFuncAttributeMaxDynamicSharedMemorySize, SMEM_BYTES);

    k_setup<<<(NN + 255) / 256, 256>>>(W1, W2);
    k_hist<<<(NE + 255) / 256, 256>>>(ei + NE);
    k_scan1<<<SCAN_NB, 1024>>>();
    k_scan2<<<1, 128>>>();
    k_scatter<<<(NE + 255) / 256, 256>>>(ei, ei + NE);

    for (int l = 0; l < 3; l++) {
        int first = (l == 0) ? 1 : 0;
        k_agg<<<(NN + 7) / 8, 256>>>(x, ea, eps, gamma, beta, l, first);
        k_mlp<<<782, 256, SMEM_BYTES>>>(l, x, masks, b1, b2, gamma, beta, first);
    }
    k_bn_apply<<<(NN * 32 + 255) / 256, 256>>>(2, out, gamma, beta);
}

// round 5
// speedup vs baseline: 1.0720x; 1.0720x over previous
#include <cuda_runtime.h>
#include <cuda_bf16.h>
#include <cuda_fp16.h>
#include <cstdint>

#define NN 100000
#define NE 1600000
#define DDIM 128
#define BN_EPS 1e-5f
#define PA 136                         // bf16 SMEM row pitch for A planes
#define SMEM_A_BYTES (2 * 128 * PA * 2)      // 69632
#define SMEM_BYTES (SMEM_A_BYTES + 65536)    // + W fragment blob = 135168
#define SCAN_NB ((NN + 1023) / 1024)   // 98

// ---------------- device scratch (static globals: allowed) ----------------
__device__ float g_h[(size_t)NN * DDIM];
__device__ float g_z[(size_t)NN * DDIM];
__device__ __nv_bfloat16 g_Ahi[(size_t)NN * DDIM];
__device__ __nv_bfloat16 g_Alo[(size_t)NN * DDIM];
__device__ int g_deg[NN];              // zero at module load; re-zeroed by k_agg(l=0)
__device__ int g_off[NN + 1];
__device__ int g_rank[NE];
__device__ int g_srcs[NE];
__device__ __half g_ea16[(size_t)NE * DDIM];   // CSR-permuted fp16 edge_attr
__device__ int g_btot[SCAN_NB];
__device__ uint32_t g_Wfrag[6 * 16384];  // 6 matrices, fragment-major
__device__ float g_bsum[3][DDIM];
__device__ float g_bsq[3][DDIM];

// ---------------- helpers ----------------
__device__ __forceinline__ void split2(float a, float b, uint32_t& hi, uint32_t& lo) {
    __nv_bfloat16 ah = __float2bfloat16(a), bh = __float2bfloat16(b);
    __nv_bfloat16 al = __float2bfloat16(a - __bfloat162float(ah));
    __nv_bfloat16 bl = __float2bfloat16(b - __bfloat162float(bh));
    __nv_bfloat162 H; H.x = ah; H.y = bh;
    __nv_bfloat162 L; L.x = al; L.y = bl;
    hi = *reinterpret_cast<uint32_t*>(&H);
    lo = *reinterpret_cast<uint32_t*>(&L);
}

__device__ __forceinline__ uint32_t lds_u32(const __nv_bfloat16* p) {
    return *reinterpret_cast<const uint32_t*>(p);
}

#define MMA16816(d0,d1,d2,d3,a0,a1,a2,a3,b0,b1)                               \
    asm volatile("mma.sync.aligned.m16n8k16.row.col.f32.bf16.bf16.f32 "       \
                 "{%0,%1,%2,%3},{%4,%5,%6,%7},{%8,%9},{%0,%1,%2,%3};"         \
                 : "+f"(d0), "+f"(d1), "+f"(d2), "+f"(d3)                     \
                 : "r"(a0), "r"(a1), "r"(a2), "r"(a3), "r"(b0), "r"(b1))

// 98-entry exclusive scan of g_btot into sBt. All threads of a 256-thread
// block must call (contains __syncthreads).
__device__ __forceinline__ void scan98_excl(int* sBt, int* ws) {
    int tid = threadIdx.x;
    int lane = tid & 31, w = tid >> 5;
    int v = 0, x = 0;
    if (tid < 128) {
        v = (tid < SCAN_NB) ? g_btot[tid] : 0;
        x = v;
#pragma unroll
        for (int d = 1; d < 32; d <<= 1) {
            int t = __shfl_up_sync(0xffffffff, x, d);
            if (lane >= d) x += t;
        }
        if (lane == 31) ws[w] = x;
    }
    __syncthreads();
    if (tid == 0) {
        int r = 0;
#pragma unroll
        for (int j = 0; j < 4; j++) { int t = ws[j]; ws[j] = r; r += t; }
    }
    __syncthreads();
    if (tid < SCAN_NB) sBt[tid] = x - v + ws[w];
    __syncthreads();
}

// ---------------- launch 1: ranks (histogram) + W split + BN zero ----------
__global__ void k_rank(const int* __restrict__ dst,
                       const float* __restrict__ W1, const float* __restrict__ W2) {
    int i = blockIdx.x * blockDim.x + threadIdx.x;
    if (i < 6 * 16384) {
        int part = i & 3;              // 0=b0h 1=b1h 2=b0l 3=b1l
        int lane = (i >> 2) & 31;
        int fragid = (i >> 7) & 127;   // nt*8 + kk
        int mat = i >> 14;             // l*2 + j
        int l = mat >> 1, j = mat & 1;
        int nt = fragid >> 3, kk = fragid & 7;
        int bn = nt * 8 + (lane >> 2);
        int bk = kk * 16 + (lane & 3) * 2 + (part & 1) * 8;
        const float* Wsrc = (j ? W2 : W1) + (size_t)l * 16384;
        float w0 = Wsrc[bk * 128 + bn];
        float w1 = Wsrc[(bk + 1) * 128 + bn];
        uint32_t hi, lo;
        split2(w0, w1, hi, lo);
        g_Wfrag[i] = (part >= 2) ? lo : hi;
    }
    if (i < 3 * DDIM) {
        ((float*)g_bsum)[i] = 0.f;
        ((float*)g_bsq)[i] = 0.f;
    }
    if (i < NE) {
        int d = __ldg(dst + i);
        g_rank[i] = atomicAdd(&g_deg[d], 1);
    }
}

// ---------------- launch 2: block-level scan of degrees --------------------
__global__ void k_scan1() {
    __shared__ int wsum[32];
    int tid = threadIdx.x, lane = tid & 31, wid = tid >> 5;
    int i = blockIdx.x * 1024 + tid;
    int v = (i < NN) ? g_deg[i] : 0;
    int x = v;
#pragma unroll
    for (int d = 1; d < 32; d <<= 1) {
        int t = __shfl_up_sync(0xffffffff, x, d);
        if (lane >= d) x += t;
    }
    if (lane == 31) wsum[wid] = x;
    __syncthreads();
    if (wid == 0) {
        int y = wsum[lane];
#pragma unroll
        for (int d = 1; d < 32; d <<= 1) {
            int t = __shfl_up_sync(0xffffffff, y, d);
            if (lane >= d) y += t;
        }
        wsum[lane] = y;
    }
    __syncthreads();
    int incl = x + (wid ? wsum[wid - 1] : 0);
    if (i < NN) g_off[i + 1] = incl;
    if (tid == 1023) g_btot[blockIdx.x] = incl;   // raw block sums
}

// ---------------- launch 3: scatter indices + permute ea -> fp16 -----------
__global__ void k_scatter(const int* __restrict__ src, const int* __restrict__ dst,
                          const float* __restrict__ ea) {
    __shared__ int sBt[SCAN_NB];
    __shared__ int ws[4];
    scan98_excl(sBt, ws);
    int gwarp = (blockIdx.x * 256 + threadIdx.x) >> 5;
    int lane = threadIdx.x & 31;
    int ebase = gwarp * 4;
    if (ebase >= NE) return;
    int pos = 0, s = 0;
    if (lane < 4 && ebase + lane < NE) {
        int e = ebase + lane;
        int d = __ldg(dst + e);
        int off = (d == 0) ? 0 : (g_off[d] + sBt[(d - 1) >> 10]);
        pos = off + g_rank[e];
        s = __ldg(src + e);
    }
    const float4* ea4 = (const float4*)ea;
#pragma unroll
    for (int k = 0; k < 4; k++) {
        int e = ebase + k;
        if (e >= NE) break;
        int p = __shfl_sync(0xffffffff, pos, k);
        if (lane == k) g_srcs[p] = s;
        float4 v = ea4[(size_t)e * 32 + lane];
        __half2 a = __float22half2_rn(make_float2(v.x, v.y));
        __half2 b = __float22half2_rn(make_float2(v.z, v.w));
        uint2 u;
        u.x = *reinterpret_cast<uint32_t*>(&a);
        u.y = *reinterpret_cast<uint32_t*>(&b);
        ((uint2*)g_ea16)[(size_t)p * 32 + lane] = u;
    }
}

// ---------------- aggregation: warp per node, sequential fp16 ea stream ----
__global__ void k_agg(const float* __restrict__ x, const float* __restrict__ eps,
                      int l, int first) {
    __shared__ int sBt[SCAN_NB];
    __shared__ int ws[4];
    scan98_excl(sBt, ws);
    int node = (blockIdx.x * blockDim.x + threadIdx.x) >> 5;
    if (node >= NN) return;
    int lane = threadIdx.x & 31;
    if (first && lane == 0) g_deg[node] = 0;     // reset for next replay
    int beg = (node == 0) ? 0 : (g_off[node] + sBt[(node - 1) >> 10]);
    int end = g_off[node + 1] + sBt[node >> 10];
    const float4* hin = (const float4*)(first ? x : g_h);
    const uint2* ea16 = (const uint2*)g_ea16;
    float4 acc = make_float4(0.f, 0.f, 0.f, 0.f);
    int i = beg;
    for (; i + 2 <= end; i += 2) {
        int s0 = g_srcs[i], s1 = g_srcs[i + 1];
        uint2 u0 = __ldcs(&ea16[(size_t)i * 32 + lane]);
        uint2 u1 = __ldcs(&ea16[(size_t)(i + 1) * 32 + lane]);
        float4 h0 = hin[(size_t)s0 * 32 + lane];
        float4 h1 = hin[(size_t)s1 * 32 + lane];
        float2 e0a = __half22float2(*(__half2*)&u0.x);
        float2 e0b = __half22float2(*(__half2*)&u0.y);
        float2 e1a = __half22float2(*(__half2*)&u1.x);
        float2 e1b = __half22float2(*(__half2*)&u1.y);
        acc.x += fmaxf(h0.x + e0a.x, 0.f) + fmaxf(h1.x + e1a.x, 0.f);
        acc.y += fmaxf(h0.y + e0a.y, 0.f) + fmaxf(h1.y + e1a.y, 0.f);
        acc.z += fmaxf(h0.z + e0b.x, 0.f) + fmaxf(h1.z + e1b.x, 0.f);
        acc.w += fmaxf(h0.w + e0b.y, 0.f) + fmaxf(h1.w + e1b.y, 0.f);
    }
    if (i < end) {
        int s0 = g_srcs[i];
        uint2 u0 = __ldcs(&ea16[(size_t)i * 32 + lane]);
        float4 h0 = hin[(size_t)s0 * 32 + lane];
        float2 e0a = __half22float2(*(__half2*)&u0.x);
        float2 e0b = __half22float2(*(__half2*)&u0.y);
        acc.x += fmaxf(h0.x + e0a.x, 0.f);
        acc.y += fmaxf(h0.y + e0a.y, 0.f);
        acc.z += fmaxf(h0.z + e0b.x, 0.f);
        acc.w += fmaxf(h0.w + e0b.y, 0.f);
    }
    float el = 1.f + __ldg(eps + l);
    float4 hn = hin[(size_t)node * 32 + lane];
    float zx = el * hn.x + acc.x;
    float zy = el * hn.y + acc.y;
    float zz = el * hn.z + acc.z;
    float zw = el * hn.w + acc.w;
    size_t o = (size_t)node * DDIM + lane * 4;
    uint32_t h01, l01, h23, l23;
    split2(zx, zy, h01, l01);
    split2(zz, zw, h23, l23);
    *(uint32_t*)(g_Ahi + o)     = h01;
    *(uint32_t*)(g_Ahi + o + 2) = h23;
    *(uint32_t*)(g_Alo + o)     = l01;
    *(uint32_t*)(g_Alo + o + 2) = l23;
}

// ---------------- fused MLP (2 GEMMs) + residual + BN partials -------------
__device__ __forceinline__ void gemm_tile(const __nv_bfloat16* __restrict__ sA_hi,
                                          const __nv_bfloat16* __restrict__ sA_lo,
                                          const uint4* __restrict__ sWf,
                                          float* acc, int lane, int mrow) {
    uint32_t ah[8][4], al[8][4];
    int r0 = mrow + (lane >> 2);
    int cb = (lane & 3) * 2;
#pragma unroll
    for (int kk = 0; kk < 8; kk++) {
        int c = kk * 16 + cb;
        ah[kk][0] = lds_u32(&sA_hi[r0 * PA + c]);
        ah[kk][1] = lds_u32(&sA_hi[(r0 + 8) * PA + c]);
        ah[kk][2] = lds_u32(&sA_hi[r0 * PA + c + 8]);
        ah[kk][3] = lds_u32(&sA_hi[(r0 + 8) * PA + c + 8]);
        al[kk][0] = lds_u32(&sA_lo[r0 * PA + c]);
        al[kk][1] = lds_u32(&sA_lo[(r0 + 8) * PA + c]);
        al[kk][2] = lds_u32(&sA_lo[r0 * PA + c + 8]);
        al[kk][3] = lds_u32(&sA_lo[(r0 + 8) * PA + c + 8]);
    }
#pragma unroll
    for (int nt = 0; nt < 16; nt++) {
        float* d = acc + nt * 4;
#pragma unroll
        for (int kk = 0; kk < 8; kk++) {
            uint4 w = sWf[(nt * 8 + kk) * 32 + lane];
            MMA16816(d[0], d[1], d[2], d[3],
                     ah[kk][0], ah[kk][1], ah[kk][2], ah[kk][3], w.x, w.y);
            MMA16816(d[0], d[1], d[2], d[3],
                     al[kk][0], al[kk][1], al[kk][2], al[kk][3], w.x, w.y);
            MMA16816(d[0], d[1], d[2], d[3],
                     ah[kk][0], ah[kk][1], ah[kk][2], ah[kk][3], w.z, w.w);
        }
    }
}

__global__ void __launch_bounds__(256, 1)
k_mlp(int l, const float* __restrict__ x, const float* __restrict__ masks,
      const float* __restrict__ b1g, const float* __restrict__ b2g, int first) {
    const float* xin = first ? x : g_h;
    extern __shared__ char smem[];
    __nv_bfloat16* sAhi = (__nv_bfloat16*)smem;
    __nv_bfloat16* sAlo = sAhi + 128 * PA;
    uint4* sWf = (uint4*)(smem + SMEM_A_BYTES);
    float* sZ = (float*)smem;   // reused after GEMM2

    int tid = threadIdx.x, lane = tid & 31, warp = tid >> 5;
    int base = blockIdx.x * 128;
    int rows = min(128, NN - base);

    // load A (z hi/lo planes), zero-fill OOB rows
    for (int i = tid; i < 128 * 64; i += 256) {
        int r = i >> 6, c2 = i & 63;
        uint32_t vh = 0, vl = 0;
        if (r < rows) {
            size_t gi = (size_t)(base + r) * 64 + c2;
            vh = ((const uint32_t*)g_Ahi)[gi];
            vl = ((const uint32_t*)g_Alo)[gi];
        }
        *(uint32_t*)(sAhi + r * PA + c2 * 2) = vh;
        *(uint32_t*)(sAlo + r * PA + c2 * 2) = vl;
    }
    {
        const uint4* wsrc = (const uint4*)(g_Wfrag + (size_t)(l * 2) * 16384);
        for (int i = tid; i < 4096; i += 256) sWf[i] = wsrc[i];
    }
    __syncthreads();

    float acc[64];
#pragma unroll
    for (int i = 0; i < 64; i++) acc[i] = 0.f;
    int mrow = warp * 16;
    gemm_tile(sAhi, sAlo, sWf, acc, lane, mrow);

    // epilogue 1: relu(acc + b1) -> hi/lo back into sA
    int r0 = mrow + (lane >> 2);
    int cb = (lane & 3) * 2;
#pragma unroll
    for (int nt = 0; nt < 16; nt++) {
        int c = nt * 8 + cb;
        float bb0 = __ldg(b1g + l * 128 + c);
        float bb1 = __ldg(b1g + l * 128 + c + 1);
        float v00 = fmaxf(acc[nt * 4 + 0] + bb0, 0.f);
        float v01 = fmaxf(acc[nt * 4 + 1] + bb1, 0.f);
        float v10 = fmaxf(acc[nt * 4 + 2] + bb0, 0.f);
        float v11 = fmaxf(acc[nt * 4 + 3] + bb1, 0.f);
        uint32_t h0, l0, h1, l1;
        split2(v00, v01, h0, l0);
        split2(v10, v11, h1, l1);
        *(uint32_t*)&sAhi[r0 * PA + c] = h0;
        *(uint32_t*)&sAlo[r0 * PA + c] = l0;
        *(uint32_t*)&sAhi[(r0 + 8) * PA + c] = h1;
        *(uint32_t*)&sAlo[(r0 + 8) * PA + c] = l1;
        acc[nt * 4 + 0] = 0.f; acc[nt * 4 + 1] = 0.f;
        acc[nt * 4 + 2] = 0.f; acc[nt * 4 + 3] = 0.f;
    }
    __syncthreads();
    {
        const uint4* wsrc = (const uint4*)(g_Wfrag + (size_t)(l * 2 + 1) * 16384);
        for (int i = tid; i < 4096; i += 256) sWf[i] = wsrc[i];
    }
    __syncthreads();

    gemm_tile(sAhi, sAlo, sWf, acc, lane, mrow);
    __syncthreads();

    // epilogue 2: z = mask * (acc + b2) + x_in
    bool ok0 = (base + r0) < NN;
    bool ok1 = (base + r0 + 8) < NN;
    float m0 = ok0 ? __ldg(masks + (size_t)l * NN + base + r0) : 0.f;
    float m1 = ok1 ? __ldg(masks + (size_t)l * NN + base + r0 + 8) : 0.f;
#pragma unroll
    for (int nt = 0; nt < 16; nt++) {
        int c = nt * 8 + cb;
        float bb0 = __ldg(b2g + l * 128 + c);
        float bb1 = __ldg(b2g + l * 128 + c + 1);
        float2 x0 = ok0 ? *(const float2*)(xin + (size_t)(base + r0) * 128 + c)
                        : make_float2(0.f, 0.f);
        float2 x1 = ok1 ? *(const float2*)(xin + (size_t)(base + r0 + 8) * 128 + c)
                        : make_float2(0.f, 0.f);
        float z00 = m0 * (acc[nt * 4 + 0] + bb0) + x0.x;
        float z01 = m0 * (acc[nt * 4 + 1] + bb1) + x0.y;
        float z10 = m1 * (acc[nt * 4 + 2] + bb0) + x1.x;
        float z11 = m1 * (acc[nt * 4 + 3] + bb1) + x1.y;
        *(float2*)&sZ[r0 * 128 + c] = make_float2(z00, z01);
        *(float2*)&sZ[(r0 + 8) * 128 + c] = make_float2(z10, z11);
    }
    __syncthreads();

    // BN column partials over valid rows
    {
        int c = tid & 127, half = tid >> 7;
        int rbeg = half * 64;
        int rend = min(rbeg + 64, rows);
        float s = 0.f, q = 0.f;
        for (int r = rbeg; r < rend; ++r) {
            float v = sZ[r * 128 + c];
            s += v; q += v * v;
        }
        atomicAdd(&g_bsum[l][c], s);
        atomicAdd(&g_bsq[l][c], q);
    }
    // write z tile
    for (int i = tid; i < rows * 32; i += 256) {
        int r = i >> 5, c4 = i & 31;
        ((float4*)(g_z + (size_t)(base + r) * 128))[c4] = ((const float4*)(sZ + r * 128))[c4];
    }
}

// ---------------- BN finalize + apply + relu ----------------
__global__ void k_bn_apply(int l, float* __restrict__ outp,
                           const float* __restrict__ gamma,
                           const float* __restrict__ beta, int last) {
    int idx = blockIdx.x * blockDim.x + threadIdx.x;
    if (idx >= NN * 32) return;
    float* o = last ? outp : g_h;
    int c4 = idx & 31;
    int c = c4 * 4;
    float4 z = ((const float4*)g_z)[idx];
    float invN = 1.f / (float)NN;
    float4 r;
    {
        float mu = g_bsum[l][c + 0] * invN;
        float var = g_bsq[l][c + 0] * invN - mu * mu;
        r.x = fmaxf(__ldg(gamma + l * 128 + c + 0) * (z.x - mu) * rsqrtf(var + BN_EPS) + __ldg(beta + l * 128 + c + 0), 0.f);
    }
    {
        float mu = g_bsum[l][c + 1] * invN;
        float var = g_bsq[l][c + 1] * invN - mu * mu;
        r.y = fmaxf(__ldg(gamma + l * 128 + c + 1) * (z.y - mu) * rsqrtf(var + BN_EPS) + __ldg(beta + l * 128 + c + 1), 0.f);
    }
    {
        float mu = g_bsum[l][c + 2] * invN;
        float var = g_bsq[l][c + 2] * invN - mu * mu;
        r.z = fmaxf(__ldg(gamma + l * 128 + c + 2) * (z.z - mu) * rsqrtf(var + BN_EPS) + __ldg(beta + l * 128 + c + 2), 0.f);
    }
    {
        float mu = g_bsum[l][c + 3] * invN;
        float var = g_bsq[l][c + 3] * invN - mu * mu;
        r.w = fmaxf(__ldg(gamma + l * 128 + c + 3) * (z.w - mu) * rsqrtf(var + BN_EPS) + __ldg(beta + l * 128 + c + 3), 0.f);
    }
    ((float4*)o)[idx] = r;
}

// ---------------- launch ----------------
extern "C" void kernel_launch(void* const* d_in, const int* in_sizes, int n_in,
                              void* d_out, int out_size) {
    const float* x     = (const float*)d_in[0];
    const float* ea    = (const float*)d_in[1];
    const float* masks = (const float*)d_in[2];
    const int*   ei    = (const int*)d_in[3];
    const float* eps   = (const float*)d_in[4];
    const float* W1    = (const float*)d_in[5];
    const float* b1    = (const float*)d_in[6];
    const float* W2    = (const float*)d_in[7];
    const float* b2    = (const float*)d_in[8];
    const float* gamma = (const float*)d_in[9];
    const float* beta  = (const float*)d_in[10];
    float* out = (float*)d_out;

    cudaFuncSetAttribute(k_mlp, cudaFuncAttributeMaxDynamicSharedMemorySize, SMEM_BYTES);

    k_rank<<<(NE + 255) / 256, 256>>>(ei + NE, W1, W2);
    k_scan1<<<SCAN_NB, 1024>>>();
    k_scatter<<<NE / 32, 256>>>(ei, ei + NE, ea);   // 50000 blocks, 4 edges/warp

    for (int l = 0; l < 3; l++) {
        int first = (l == 0) ? 1 : 0;
        int last = (l == 2) ? 1 : 0;
        k_agg<<<(NN + 7) / 8, 256>>>(x, eps, l, first);
        k_mlp<<<782, 256, SMEM_BYTES>>>(l, x, masks, b1, b2, first);
        k_bn_apply<<<(NN * 32 + 255) / 256, 256>>>(l, out, gamma, beta, last);
    }
}